// round 12
// baseline (speedup 1.0000x reference)
#include <cuda_runtime.h>

// Problem constants
#define G_   512
#define N_   512
#define E_   2048
#define F_   64
#define D1_  128
#define D2_  64
#define L_   32
#define P_   16384
#define NB_  32          // adj-build blocks (P_/512)
#define NSTAGE_ 128      // nodes staged to smem during the atomic phase

// ---------------- device scratch (no allocations allowed) ----------------
__device__ float g_A[G_ * G_];        // dense VGAE adjacency counts (dst-major).
                                      // Invariant: zero at kernel_launch entry;
                                      // gather2 re-zeroes rows after last use.
__device__ float g_t1[G_ * D1_];      // dinv2[g] * (emb[g,:] @ conv1_W)
__device__ float g_t2[G_ * D2_];      // dinv2[m] * (relu_row @ mu_W)

// ---------------- dense adjacency build (replaces count/scan/scatter) ----
__global__ void __launch_bounds__(512) adj_kernel(const int* __restrict__ pos_edges)
{
    const int e = blockIdx.x * 512 + threadIdx.x;
    const int s = __ldg(&pos_edges[e]);
    const int d = __ldg(&pos_edges[P_ + e]);
    atomicAdd(&g_A[d * G_ + s], 1.0f);   // scattered: ~no contention
}

// ---------------- fused SAGE (R11 skeleton + inline dinv2 from A row) -----
// Prologue: all threads issue stage loads (nodes 0..127) + edge loads + own
// A-row element FIRST, then do their 8 smem atomics in parallel — LDG latency
// and DRAM traffic overlap the atomic phase. Phase B: staged nodes from smem,
// rest streamed float4. Then emb/t1 GEMVs; t1 scaled by dinv2 = rsqrt(rowsum+1).
__global__ void __launch_bounds__(512, 2) sage_kernel(
    const float* __restrict__ features,
    const int*   __restrict__ edges,
    const float* __restrict__ W1,
    const float* __restrict__ b1,
    const float* __restrict__ conv1_W)
{
    const int g   = blockIdx.x;
    const int tid = threadIdx.x;

    __shared__ float s_stage[NSTAGE_ * F_];   // 32 KB: nodes 0..127
    __shared__ int   s_deg[N_];               // 2 KB
    __shared__ float s_dinv[N_];              // 2 KB
    __shared__ float s_accw[N_];              // 2 KB: acc, then w (own-slot)
    __shared__ float s_part[32 * F_];         // 8 KB, reused by GEMVs
    __shared__ float s_v[F_];
    __shared__ float s_emb[D1_];
    __shared__ float s_red[16];               // per-warp A-row partial sums

    const float4* x4   = (const float4*)(features + (size_t)g * N_ * F_);
    const int*    src  = edges + (size_t)g * 2 * E_;
    const int4*   src4 = (const int4*)src;
    const int4*   dst4 = (const int4*)(src + E_);

    s_deg[tid]  = 1;                          // self loop
    s_accw[tid] = 0.f;

    // ---- issue independent loads FIRST: stage float4s + edges + A row ----
    float4 r0 = __ldg(&x4[tid]);
    float4 r1 = __ldg(&x4[tid + 512]);
    float4 r2 = __ldg(&x4[tid + 1024]);
    float4 r3 = __ldg(&x4[tid + 1536]);
    const int4 d4 = __ldg(&dst4[tid]);
    const int4 s4 = __ldg(&src4[tid]);
    float av = __ldg(&g_A[(size_t)g * G_ + tid]);   // VGAE in-degree row
    #pragma unroll
    for (int o = 16; o > 0; o >>= 1)
        av += __shfl_xor_sync(0xffffffffu, av, o);
    if ((tid & 31) == 0) s_red[tid >> 5] = av;
    __syncthreads();                          // deg/acc init + s_red visible

    // ---- parallel atomics, overlapped with the loads above ---------------
    atomicAdd(&s_deg[d4.x], 1);
    atomicAdd(&s_deg[d4.y], 1);
    atomicAdd(&s_deg[d4.z], 1);
    atomicAdd(&s_deg[d4.w], 1);
    __syncthreads();

    s_dinv[tid] = rsqrtf((float)s_deg[tid]);
    __syncthreads();

    atomicAdd(&s_accw[s4.x], s_dinv[d4.x]);
    atomicAdd(&s_accw[s4.y], s_dinv[d4.y]);
    atomicAdd(&s_accw[s4.z], s_dinv[d4.z]);
    atomicAdd(&s_accw[s4.w], s_dinv[d4.w]);

    // ---- store staged features (regs -> smem), then finish w -------------
    {
        float4* st4 = (float4*)s_stage;
        st4[tid]        = r0;
        st4[tid + 512]  = r1;
        st4[tid + 1024] = r2;
        st4[tid + 1536] = r3;
    }
    __syncthreads();
    {
        const float wn = s_dinv[tid] * (s_accw[tid] + s_dinv[tid]);
        __syncthreads();
        s_accw[tid] = wn;                     // own-slot rewrite
    }
    __syncthreads();

    // ---- weighted reduce: v[f] = sum_n w[n]*x[n,f] -----------------------
    {
        const int lane = tid & 15;
        const int grp  = tid >> 4;
        float4 acc = make_float4(0.f, 0.f, 0.f, 0.f);
        #pragma unroll
        for (int j = 4; j < 16; j++) {
            const int n = grp + j * 32;
            const float wn = s_accw[n];
            const float4 xv = __ldg(&x4[n * 16 + lane]);
            acc.x += wn * xv.x;
            acc.y += wn * xv.y;
            acc.z += wn * xv.z;
            acc.w += wn * xv.w;
        }
        #pragma unroll
        for (int j = 0; j < 4; j++) {
            const int n = grp + j * 32;
            const float wn = s_accw[n];
            const float4 xv = *(const float4*)&s_stage[n * F_ + lane * 4];
            acc.x += wn * xv.x;
            acc.y += wn * xv.y;
            acc.z += wn * xv.z;
            acc.w += wn * xv.w;
        }
        float* pp = &s_part[grp * F_ + lane * 4];
        pp[0] = acc.x; pp[1] = acc.y; pp[2] = acc.z; pp[3] = acc.w;
    }
    __syncthreads();
    if (tid < F_) {
        float v = 0.f;
        #pragma unroll
        for (int gr = 0; gr < 32; gr++) v += s_part[gr * F_ + tid];
        s_v[tid] = v;
    }
    __syncthreads();

    // emb: 512 threads = 128 d x 4 h, each 16 ff
    {
        const int d = tid & 127, h = tid >> 7;
        float a = 0.f;
        #pragma unroll
        for (int k = 0; k < 16; k++) {
            const int ff = h * 16 + k;
            a += s_v[ff] * __ldg(&W1[ff * D1_ + d]);
        }
        s_part[h * D1_ + d] = a;
    }
    __syncthreads();
    if (tid < D1_) {
        const float a = s_part[tid] + s_part[D1_ + tid] + s_part[2 * D1_ + tid]
                      + s_part[3 * D1_ + tid] + 512.0f * __ldg(&b1[tid]);
        s_emb[tid] = a * (1.0f / 16.0f);
    }
    __syncthreads();

    // t1: 128 d x 4 h, each 32 ff
    {
        const int d = tid & 127, h = tid >> 7;
        float a = 0.f;
        #pragma unroll 8
        for (int k = 0; k < 32; k++) {
            const int ff = h * 32 + k;
            a += s_emb[ff] * __ldg(&conv1_W[ff * D1_ + d]);
        }
        s_part[h * D1_ + d] = a;
    }
    __syncthreads();
    if (tid < D1_) {
        float deg = 0.f;
        #pragma unroll
        for (int w = 0; w < 16; w++) deg += s_red[w];
        const float dv = rsqrtf(deg + 1.0f);          // +1 self loop
        g_t1[g * D1_ + tid] = dv * (s_part[tid] + s_part[D1_ + tid]
                                  + s_part[2 * D1_ + tid] + s_part[3 * D1_ + tid]);
    }
}

// ---------------- conv1 gather (dense A row) + relu + mu matmul -----------
__global__ void __launch_bounds__(512) gather1_kernel(
    const float* __restrict__ conv1_b,
    const float* __restrict__ mu_W)
{
    const int m   = blockIdx.x;
    const int tid = threadIdx.x;
    __shared__ float s_a[G_];             // 2 KB: A row m
    __shared__ float s_part[4 * D1_];     // 512 floats (also 8*64 for mu GEMV)
    __shared__ float s_row[D1_];
    __shared__ float s_red[16];

    float av = __ldg(&g_A[(size_t)m * G_ + tid]);
    s_a[tid] = av;
    #pragma unroll
    for (int o = 16; o > 0; o >>= 1)
        av += __shfl_xor_sync(0xffffffffu, av, o);
    if ((tid & 31) == 0) s_red[tid >> 5] = av;
    __syncthreads();

    float deg = 0.f;
    #pragma unroll
    for (int w = 0; w < 16; w++) deg += s_red[w];
    const float dv = rsqrtf(deg + 1.0f);

    // weighted neighbor sum: 4 slices x 128 cols; warp-uniform nonzero skip
    {
        const int d = tid & 127, slice = tid >> 7;
        const int s0 = slice * 128;
        float acc = 0.f;
        for (int s = s0; s < s0 + 128; s++) {
            const float a = s_a[s];
            if (a != 0.f) acc += a * __ldg(&g_t1[s * D1_ + d]);
        }
        s_part[slice * D1_ + d] = acc;
    }
    __syncthreads();
    if (tid < D1_) {
        const float tot = s_part[tid] + s_part[D1_ + tid] + s_part[2 * D1_ + tid]
                        + s_part[3 * D1_ + tid] + g_t1[m * D1_ + tid];
        s_row[tid] = fmaxf(dv * tot + __ldg(&conv1_b[tid]), 0.f);
    }
    __syncthreads();

    // t2 = row @ mu_W : 64 d2 x 8 h, each 16 ff
    {
        const int d2 = tid & 63, h = tid >> 6;
        float a = 0.f;
        #pragma unroll
        for (int k = 0; k < 16; k++) {
            const int ff = h * 16 + k;
            a += s_row[ff] * __ldg(&mu_W[ff * D2_ + d2]);
        }
        s_part[h * D2_ + d2] = a;
    }
    __syncthreads();
    if (tid < D2_) {
        float t = 0.f;
        #pragma unroll
        for (int hh = 0; hh < 8; hh++) t += s_part[hh * D2_ + tid];
        g_t2[m * D2_ + tid] = dv * t;
    }
}

// ---------------- mu gather + classifier + log_softmax (+A re-zero) -------
__global__ void __launch_bounds__(512) gather2_kernel(
    const float* __restrict__ mu_b,
    const float* __restrict__ clf_W,
    const float* __restrict__ clf_b,
    float* __restrict__ out)
{
    const int m   = blockIdx.x;
    const int tid = threadIdx.x;
    __shared__ float s_a[G_];
    __shared__ float s_part[8 * D2_];
    __shared__ float s_mu[D2_];
    __shared__ float s_lp[8 * L_];
    __shared__ float s_red[16];

    float av = __ldg(&g_A[(size_t)m * G_ + tid]);
    s_a[tid] = av;
    g_A[(size_t)m * G_ + tid] = 0.f;      // restore invariant (last reader)
    #pragma unroll
    for (int o = 16; o > 0; o >>= 1)
        av += __shfl_xor_sync(0xffffffffu, av, o);
    if ((tid & 31) == 0) s_red[tid >> 5] = av;
    __syncthreads();

    float deg = 0.f;
    #pragma unroll
    for (int w = 0; w < 16; w++) deg += s_red[w];
    const float dv = rsqrtf(deg + 1.0f);

    // weighted neighbor sum: 8 slices x 64 cols; warp-uniform nonzero skip
    {
        const int d = tid & 63, slice = tid >> 6;
        const int s0 = slice * 64;
        float acc = 0.f;
        for (int s = s0; s < s0 + 64; s++) {
            const float a = s_a[s];
            if (a != 0.f) acc += a * __ldg(&g_t2[s * D2_ + d]);
        }
        s_part[slice * D2_ + d] = acc;
    }
    __syncthreads();
    if (tid < D2_) {
        float tot = g_t2[m * D2_ + tid];
        #pragma unroll
        for (int s = 0; s < 8; s++) tot += s_part[s * D2_ + tid];
        s_mu[tid] = dv * tot + __ldg(&mu_b[tid]);
    }
    __syncthreads();

    // logits: 32 l x 8 h, each 8 ff
    if (tid < 256) {
        const int l = tid & 31, h = tid >> 5;
        float a = 0.f;
        #pragma unroll
        for (int k = 0; k < 8; k++) {
            const int ff = h * 8 + k;
            a += s_mu[ff] * __ldg(&clf_W[ff * L_ + l]);
        }
        s_lp[h * L_ + l] = a;
    }
    __syncthreads();
    if (tid < L_) {                 // warp 0: reduce + log_softmax
        float a = __ldg(&clf_b[tid]);
        #pragma unroll
        for (int h = 0; h < 8; h++) a += s_lp[h * L_ + tid];
        float mx = a;
        #pragma unroll
        for (int o = 16; o > 0; o >>= 1)
            mx = fmaxf(mx, __shfl_xor_sync(0xffffffffu, mx, o));
        const float ex = expf(a - mx);
        float sm = ex;
        #pragma unroll
        for (int o = 16; o > 0; o >>= 1)
            sm += __shfl_xor_sync(0xffffffffu, sm, o);
        out[m * L_ + tid] = a - mx - logf(sm);
    }
}

// --------------------------------------------------------------------------
extern "C" void kernel_launch(void* const* d_in, const int* in_sizes, int n_in,
                              void* d_out, int out_size)
{
    const float* features = (const float*)d_in[0];
    const int*   edges    = (const int*)  d_in[1];
    const int*   pos_e    = (const int*)  d_in[2];
    const float* W1       = (const float*)d_in[3];
    const float* b1       = (const float*)d_in[4];
    // d_in[5..8]: fc1_W, fc1_b, fc2_W, fc2_b — mathematically dead (softmax rows sum to 1)
    const float* conv1_W  = (const float*)d_in[9];
    const float* conv1_b  = (const float*)d_in[10];
    const float* mu_W     = (const float*)d_in[11];
    const float* mu_b     = (const float*)d_in[12];
    const float* clf_W    = (const float*)d_in[13];
    const float* clf_b    = (const float*)d_in[14];
    float* out = (float*)d_out;

    adj_kernel    <<<NB_, 512>>>(pos_e);
    sage_kernel   <<<G_,  512>>>(features, edges, W1, b1, conv1_W);
    gather1_kernel<<<G_,  512>>>(conv1_b, mu_W);
    gather2_kernel<<<G_,  512>>>(mu_b, clf_W, clf_b, out);
}

// round 13
// speedup vs baseline: 1.2071x; 1.2071x over previous
#include <cuda_runtime.h>

// Problem constants
#define G_   512
#define N_   512
#define E_   2048
#define F_   64
#define D1_  128
#define D2_  64
#define L_   32
#define P_   16384
#define NB_  32          // CSR build blocks (P_/512)
#define MAXDEG_ 256
#define NSTAGE_ 64       // nodes staged to smem during the atomic phase

// ---------------- device scratch (no allocations allowed) ----------------
__device__ float g_t1[G_ * D1_];      // dinv2[g] * (emb[g,:] @ conv1_W)
__device__ float g_t2[G_ * D2_];      // dinv2[m] * (relu_row @ mu_W)
__device__ int   g_off[G_ + 1];
__device__ float g_dinv2[G_];
__device__ int   g_srcbuf[P_];
__device__ int   g_partial[NB_][G_];  // per-block dst histograms
__device__ int   g_base[NB_][G_];     // per-(block,dst) starting slot

// ---------------- CSR build: count (privatized, no global atomics) --------
__global__ void __launch_bounds__(512) count_kernel(const int* __restrict__ pos_edges)
{
    __shared__ int s_cnt[G_];
    const int b = blockIdx.x, tid = threadIdx.x;
    s_cnt[tid] = 0;
    __syncthreads();
    const int d = __ldg(&pos_edges[P_ + b * 512 + tid]);
    atomicAdd(&s_cnt[d], 1);
    __syncthreads();
    g_partial[b][tid] = s_cnt[tid];
}

// ---------------- CSR build: scan + per-block bases -----------------------
__global__ void __launch_bounds__(512) scan_kernel()
{
    const int tid = threadIdx.x;
    int part[NB_];
    int c = 0;
    #pragma unroll
    for (int b = 0; b < NB_; b++) { part[b] = g_partial[b][tid]; c += part[b]; }
    g_dinv2[tid] = rsqrtf((float)(c + 1));       // +1 self loop

    const int lane = tid & 31, w = tid >> 5;
    int v = c;
    #pragma unroll
    for (int o = 1; o < 32; o <<= 1) {
        int t = __shfl_up_sync(0xffffffffu, v, o);
        if (lane >= o) v += t;
    }
    __shared__ int wsum[16];
    if (lane == 31) wsum[w] = v;
    __syncthreads();
    if (tid < 16) {
        int x = wsum[tid];
        #pragma unroll
        for (int o = 1; o < 16; o <<= 1) {
            int t = __shfl_up_sync(0x0000ffffu, x, o);
            if (tid >= o) x += t;
        }
        wsum[tid] = x;
    }
    __syncthreads();
    const int incl = v + (w > 0 ? wsum[w - 1] : 0);
    const int excl = incl - c;
    g_off[tid + 1] = incl;
    if (tid == 0) g_off[0] = 0;

    int base = excl;
    #pragma unroll
    for (int b = 0; b < NB_; b++) { g_base[b][tid] = base; base += part[b]; }
}

// ---------------- CSR build: scatter (smem rank counters only) ------------
__global__ void __launch_bounds__(512) scatter_kernel(const int* __restrict__ pos_edges)
{
    __shared__ int s_fill[G_];
    const int b = blockIdx.x, tid = threadIdx.x;
    s_fill[tid] = 0;
    __syncthreads();
    const int e = b * 512 + tid;
    const int d = __ldg(&pos_edges[P_ + e]);
    const int s = __ldg(&pos_edges[e]);
    const int r = atomicAdd(&s_fill[d], 1);      // rank within block
    g_srcbuf[g_base[b][d] + r] = s;
}

// ---------------- fused SAGE: 256 thr, 4 blocks/SM, single wave -----------
// Overlapped staging (R11 mechanism): all threads issue stage float4 loads
// (nodes 0..63) + edge loads FIRST, then parallel smem atomics. Phase B:
// staged nodes from smem, rest streamed float4. Then emb/t1 GEMVs.
__global__ void __launch_bounds__(256, 4) sage_kernel(
    const float* __restrict__ features,
    const int*   __restrict__ edges,
    const float* __restrict__ W1,
    const float* __restrict__ b1,
    const float* __restrict__ conv1_W)
{
    const int g   = blockIdx.x;
    const int tid = threadIdx.x;

    __shared__ float s_stage[NSTAGE_ * F_];   // 16 KB: nodes 0..63
    __shared__ int   s_deg[N_];               // 2 KB
    __shared__ float s_dinv[N_];              // 2 KB
    __shared__ float s_accw[N_];              // 2 KB: acc, then w (own-slot)
    __shared__ float s_part[16 * F_];         // 4 KB, reused by GEMVs
    __shared__ float s_v[F_];
    __shared__ float s_emb[D1_];

    const float4* x4   = (const float4*)(features + (size_t)g * N_ * F_);
    const int*    src  = edges + (size_t)g * 2 * E_;
    const int4*   src4 = (const int4*)src;
    const int4*   dst4 = (const int4*)(src + E_);

    s_deg[tid]        = 1;  s_deg[tid + 256]  = 1;    // self loop
    s_accw[tid]       = 0.f; s_accw[tid + 256] = 0.f;

    // ---- issue independent loads FIRST: 4 stage float4 + 4 edge int4 -----
    float4 r0 = __ldg(&x4[tid]);
    float4 r1 = __ldg(&x4[tid + 256]);
    float4 r2 = __ldg(&x4[tid + 512]);
    float4 r3 = __ldg(&x4[tid + 768]);
    const int4 da = __ldg(&dst4[tid]);
    const int4 db = __ldg(&dst4[tid + 256]);
    const int4 sa = __ldg(&src4[tid]);
    const int4 sb = __ldg(&src4[tid + 256]);
    __syncthreads();                          // deg/acc init visible

    // ---- parallel atomics, overlapped with the loads above ---------------
    atomicAdd(&s_deg[da.x], 1); atomicAdd(&s_deg[da.y], 1);
    atomicAdd(&s_deg[da.z], 1); atomicAdd(&s_deg[da.w], 1);
    atomicAdd(&s_deg[db.x], 1); atomicAdd(&s_deg[db.y], 1);
    atomicAdd(&s_deg[db.z], 1); atomicAdd(&s_deg[db.w], 1);
    __syncthreads();

    s_dinv[tid]       = rsqrtf((float)s_deg[tid]);
    s_dinv[tid + 256] = rsqrtf((float)s_deg[tid + 256]);
    __syncthreads();

    atomicAdd(&s_accw[sa.x], s_dinv[da.x]);
    atomicAdd(&s_accw[sa.y], s_dinv[da.y]);
    atomicAdd(&s_accw[sa.z], s_dinv[da.z]);
    atomicAdd(&s_accw[sa.w], s_dinv[da.w]);
    atomicAdd(&s_accw[sb.x], s_dinv[db.x]);
    atomicAdd(&s_accw[sb.y], s_dinv[db.y]);
    atomicAdd(&s_accw[sb.z], s_dinv[db.z]);
    atomicAdd(&s_accw[sb.w], s_dinv[db.w]);

    // ---- store staged features (regs -> smem), then finish w -------------
    {
        float4* st4 = (float4*)s_stage;
        st4[tid]       = r0;
        st4[tid + 256] = r1;
        st4[tid + 512] = r2;
        st4[tid + 768] = r3;
    }
    __syncthreads();
    {
        const float w0 = s_dinv[tid]       * (s_accw[tid]       + s_dinv[tid]);
        const float w1 = s_dinv[tid + 256] * (s_accw[tid + 256] + s_dinv[tid + 256]);
        __syncthreads();
        s_accw[tid]       = w0;               // own-slot rewrite
        s_accw[tid + 256] = w1;
    }
    __syncthreads();

    // ---- weighted reduce: v[f] = sum_n w[n]*x[n,f] -----------------------
    // 16 row-groups x 16 float4-lanes. n = grp + 16*j, j = 0..31;
    // j<4 -> staged smem (n<64), j>=4 -> direct global stream.
    {
        const int lane = tid & 15;
        const int grp  = tid >> 4;
        float4 acc = make_float4(0.f, 0.f, 0.f, 0.f);
        #pragma unroll 4
        for (int j = 4; j < 32; j++) {
            const int n = grp + j * 16;
            const float wn = s_accw[n];
            const float4 xv = __ldg(&x4[n * 16 + lane]);
            acc.x += wn * xv.x;
            acc.y += wn * xv.y;
            acc.z += wn * xv.z;
            acc.w += wn * xv.w;
        }
        #pragma unroll
        for (int j = 0; j < 4; j++) {
            const int n = grp + j * 16;
            const float wn = s_accw[n];
            const float4 xv = *(const float4*)&s_stage[n * F_ + lane * 4];
            acc.x += wn * xv.x;
            acc.y += wn * xv.y;
            acc.z += wn * xv.z;
            acc.w += wn * xv.w;
        }
        float* pp = &s_part[grp * F_ + lane * 4];
        pp[0] = acc.x; pp[1] = acc.y; pp[2] = acc.z; pp[3] = acc.w;
    }
    __syncthreads();
    if (tid < F_) {
        float v = 0.f;
        #pragma unroll
        for (int gr = 0; gr < 16; gr++) v += s_part[gr * F_ + tid];
        s_v[tid] = v;
    }
    __syncthreads();

    // emb: 256 threads = 128 d x 2 h, each 32 ff
    {
        const int d = tid & 127, h = tid >> 7;
        float a = 0.f;
        #pragma unroll 8
        for (int k = 0; k < 32; k++) {
            const int ff = h * 32 + k;
            a += s_v[ff] * __ldg(&W1[ff * D1_ + d]);
        }
        s_part[h * D1_ + d] = a;
    }
    __syncthreads();
    if (tid < D1_) {
        const float a = s_part[tid] + s_part[D1_ + tid] + 512.0f * __ldg(&b1[tid]);
        s_emb[tid] = a * (1.0f / 16.0f);
    }
    __syncthreads();

    // t1: 128 d x 2 h, each 64 ff
    {
        const int d = tid & 127, h = tid >> 7;
        float a = 0.f;
        #pragma unroll 8
        for (int k = 0; k < 64; k++) {
            const int ff = h * 64 + k;
            a += s_emb[ff] * __ldg(&conv1_W[ff * D1_ + d]);
        }
        s_part[h * D1_ + d] = a;
    }
    __syncthreads();
    if (tid < D1_) {
        const float dv = __ldg(&g_dinv2[g]);
        g_t1[g * D1_ + tid] = dv * (s_part[tid] + s_part[D1_ + tid]);
    }
}

// ---------------- conv1 gather + relu + mu matmul (fused) -----------------
__global__ void __launch_bounds__(512) gather1_kernel(
    const float* __restrict__ conv1_b,
    const float* __restrict__ mu_W)
{
    const int m   = blockIdx.x;
    const int tid = threadIdx.x;
    __shared__ float s_part[8 * D2_];     // 512 floats (also holds 4*128)
    __shared__ float s_row[D1_];
    __shared__ int   s_idx[MAXDEG_];

    const int beg = g_off[m], end = g_off[m + 1];
    int deg = end - beg;
    if (deg > MAXDEG_) deg = MAXDEG_;     // statistically unreachable; safety
    for (int i = tid; i < deg; i += 512) s_idx[i] = __ldg(&g_srcbuf[beg + i]);
    __syncthreads();

    {
        const int d = tid & 127, slice = tid >> 7;
        float acc = 0.f;
        #pragma unroll 4
        for (int i = slice; i < deg; i += 4)
            acc += __ldg(&g_t1[s_idx[i] * D1_ + d]);
        s_part[slice * D1_ + d] = acc;
    }
    __syncthreads();
    const float dv = g_dinv2[m];
    if (tid < D1_) {
        const float tot = s_part[tid] + s_part[D1_ + tid] + s_part[2 * D1_ + tid]
                        + s_part[3 * D1_ + tid] + g_t1[m * D1_ + tid];
        s_row[tid] = fmaxf(dv * tot + __ldg(&conv1_b[tid]), 0.f);
    }
    __syncthreads();

    {
        const int d2 = tid & 63, h = tid >> 6;
        float a = 0.f;
        #pragma unroll
        for (int k = 0; k < 16; k++) {
            const int ff = h * 16 + k;
            a += s_row[ff] * __ldg(&mu_W[ff * D2_ + d2]);
        }
        s_part[h * D2_ + d2] = a;
    }
    __syncthreads();
    if (tid < D2_) {
        float t = 0.f;
        #pragma unroll
        for (int hh = 0; hh < 8; hh++) t += s_part[hh * D2_ + tid];
        g_t2[m * D2_ + tid] = dv * t;
    }
}

// ---------------- mu gather + classifier + log_softmax (fused) ------------
__global__ void __launch_bounds__(512) gather2_kernel(
    const float* __restrict__ mu_b,
    const float* __restrict__ clf_W,
    const float* __restrict__ clf_b,
    float* __restrict__ out)
{
    const int m   = blockIdx.x;
    const int tid = threadIdx.x;
    __shared__ float s_part[8 * D2_];
    __shared__ float s_mu[D2_];
    __shared__ float s_lp[8 * L_];
    __shared__ int   s_idx[MAXDEG_];

    const int beg = g_off[m], end = g_off[m + 1];
    int deg = end - beg;
    if (deg > MAXDEG_) deg = MAXDEG_;
    for (int i = tid; i < deg; i += 512) s_idx[i] = __ldg(&g_srcbuf[beg + i]);
    __syncthreads();

    {
        const int d = tid & 63, slice = tid >> 6;
        float acc = 0.f;
        #pragma unroll 4
        for (int i = slice; i < deg; i += 8)
            acc += __ldg(&g_t2[s_idx[i] * D2_ + d]);
        s_part[slice * D2_ + d] = acc;
    }
    __syncthreads();
    if (tid < D2_) {
        float tot = g_t2[m * D2_ + tid];
        #pragma unroll
        for (int s = 0; s < 8; s++) tot += s_part[s * D2_ + tid];
        s_mu[tid] = g_dinv2[m] * tot + __ldg(&mu_b[tid]);
    }
    __syncthreads();

    if (tid < 256) {
        const int l = tid & 31, h = tid >> 5;
        float a = 0.f;
        #pragma unroll
        for (int k = 0; k < 8; k++) {
            const int ff = h * 8 + k;
            a += s_mu[ff] * __ldg(&clf_W[ff * L_ + l]);
        }
        s_lp[h * L_ + l] = a;
    }
    __syncthreads();
    if (tid < L_) {
        float a = __ldg(&clf_b[tid]);
        #pragma unroll
        for (int h = 0; h < 8; h++) a += s_lp[h * L_ + tid];
        float mx = a;
        #pragma unroll
        for (int o = 16; o > 0; o >>= 1)
            mx = fmaxf(mx, __shfl_xor_sync(0xffffffffu, mx, o));
        const float ex = expf(a - mx);
        float sm = ex;
        #pragma unroll
        for (int o = 16; o > 0; o >>= 1)
            sm += __shfl_xor_sync(0xffffffffu, sm, o);
        out[m * L_ + tid] = a - mx - logf(sm);
    }
}

// --------------------------------------------------------------------------
extern "C" void kernel_launch(void* const* d_in, const int* in_sizes, int n_in,
                              void* d_out, int out_size)
{
    const float* features = (const float*)d_in[0];
    const int*   edges    = (const int*)  d_in[1];
    const int*   pos_e    = (const int*)  d_in[2];
    const float* W1       = (const float*)d_in[3];
    const float* b1       = (const float*)d_in[4];
    // d_in[5..8]: fc1_W, fc1_b, fc2_W, fc2_b — mathematically dead (softmax rows sum to 1)
    const float* conv1_W  = (const float*)d_in[9];
    const float* conv1_b  = (const float*)d_in[10];
    const float* mu_W     = (const float*)d_in[11];
    const float* mu_b     = (const float*)d_in[12];
    const float* clf_W    = (const float*)d_in[13];
    const float* clf_b    = (const float*)d_in[14];
    float* out = (float*)d_out;

    count_kernel  <<<NB_, 512>>>(pos_e);
    scan_kernel   <<<1,   512>>>();
    scatter_kernel<<<NB_, 512>>>(pos_e);
    sage_kernel   <<<G_,  256>>>(features, edges, W1, b1, conv1_W);
    gather1_kernel<<<G_,  512>>>(conv1_b, mu_W);
    gather2_kernel<<<G_,  512>>>(mu_b, clf_W, clf_b, out);
}